// round 2
// baseline (speedup 1.0000x reference)
#include <cuda_runtime.h>

#define GRID_NUM 7
#define CELLS_PER_IMG 49
#define IMG_SIZE 448.0f
#define GRID_SIZE 64.0f
#define LAMBDA_COORD 5.0f
#define LAMBDA_NOOBJ 0.1f
#define EPSF 1e-12f

#define TILE 256          // cells per tile == blockDim
#define MAX_BLOCKS 2048

__device__ float g_partials[MAX_BLOCKS];

__device__ __forceinline__ float iou_f(float bx, float by, float bw, float bh,
                                       float tx, float ty, float tw, float th,
                                       float gi, float gj) {
    float cx_p = bx * GRID_SIZE + gj * GRID_SIZE;
    float cy_p = by * GRID_SIZE + gi * GRID_SIZE;
    float w_p = bw * IMG_SIZE;
    float h_p = bh * IMG_SIZE;
    float x0p = cx_p - w_p * 0.5f, x1p = cx_p + w_p * 0.5f;
    float y0p = cy_p - h_p * 0.5f, y1p = cy_p + h_p * 0.5f;
    float cx_t = tx * GRID_SIZE + gj * GRID_SIZE;
    float cy_t = ty * GRID_SIZE + gi * GRID_SIZE;
    float w_t = tw * IMG_SIZE;
    float h_t = th * IMG_SIZE;
    float x0t = cx_t - w_t * 0.5f, x1t = cx_t + w_t * 0.5f;
    float y0t = cy_t - h_t * 0.5f;
    float y1t = cy_t + w_t * 0.5f;   // TYPO kept from reference: uses w_t
    float ux0 = fmaxf(x0p, x0t);
    float ux1 = fminf(x1p, x1t);
    float uy0 = fmaxf(y0p, y0t);
    float uy1 = fminf(y1p, y1t);
    bool valid = (ux0 < ux1) && (uy0 < uy1);
    float area_u = (ux1 - ux0) * (uy1 - uy0);
    float area_p = (x1p - x0p) * (y1p - y0p);
    float area_t = (x1t - x0t) * (y1t - y0t);
    float res = area_u / (area_p + area_t - area_u + EPSF);
    return valid ? res : 0.0f;
}

__device__ __forceinline__ float cell_loss(const float* __restrict__ sp,
                                           const float* __restrict__ st,
                                           int cell_idx) {
    int g = cell_idx % CELLS_PER_IMG;
    float gi = (float)(g / GRID_NUM);
    float gj = (float)(g % GRID_NUM);

    float p0 = sp[0], p1 = sp[1], p2 = sp[2], p3 = sp[3], p4 = sp[4];
    float p5 = sp[5], p6 = sp[6], p7 = sp[7], p8 = sp[8], p9 = sp[9];
    float t0 = st[0], t1 = st[1], t2 = st[2], t3 = st[3], t4 = st[4];

    float iou0 = iou_f(p0, p1, p2, p3, t0, t1, t2, t3, gi, gj);
    float iou1 = iou_f(p5, p6, p7, p8, t0, t1, t2, t3, gi, gj);

    bool obj = (t4 == 1.0f);
    bool c0 = iou0 > iou1;

    float local;
    if (obj) {
        float conf_pre = c0 ? p4 : p9;
        float conf_true = c0 ? iou0 : iou1;
        float dc = conf_pre - conf_true;
        local = dc * dc;
        float xb = c0 ? p0 : p5;
        float yb = c0 ? p1 : p6;
        float dx = xb - t0;
        float dy = yb - t1;
        local += LAMBDA_COORD * (dx * dx + dy * dy);
        float wb = fmaxf(c0 ? p2 : p7, EPSF);
        float hb = fmaxf(c0 ? p3 : p8, EPSF);
        float wt = fmaxf(t2, EPSF);
        float ht = fmaxf(t3, EPSF);
        float dw = sqrtf(wb) - sqrtf(wt);
        float dh = sqrtf(hb) - sqrtf(ht);
        local += LAMBDA_COORD * (dw * dw + dh * dh);
    } else {
        local = LAMBDA_NOOBJ * (p4 * p4 + p9 * p9);
    }
    return local;
}

__global__ void __launch_bounds__(TILE)
yolo_loss_kernel(const float* __restrict__ y_pre,
                 const float* __restrict__ y_true,
                 int n_cells, int n_tiles) {
    __shared__ float s_pre[TILE * 10];   // 10240 B
    __shared__ float s_true[TILE * 5];   // 5120 B

    int tid = threadIdx.x;
    float acc = 0.0f;

    for (int tile = blockIdx.x; tile < n_tiles; tile += gridDim.x) {
        int base = tile * TILE;
        int rem = n_cells - base;                  // cells in this tile

        if (rem >= TILE) {
            // fully coalesced float4 staging
            const float4* gp = (const float4*)(y_pre + (size_t)base * 10);
            float4* sp4 = (float4*)s_pre;
            #pragma unroll
            for (int i = 0; i < 2; i++)
                sp4[tid + i * TILE] = gp[tid + i * TILE];
            if (tid < (TILE * 10 / 4) - 2 * TILE)
                sp4[tid + 2 * TILE] = gp[tid + 2 * TILE];

            const float4* gt = (const float4*)(y_true + (size_t)base * 5);
            float4* st4 = (float4*)s_true;
            st4[tid] = gt[tid];
            if (tid < (TILE * 5 / 4) - TILE)
                st4[tid + TILE] = gt[tid + TILE];
        } else {
            // tail tile: scalar staging with bounds
            for (int i = tid; i < rem * 10; i += TILE)
                s_pre[i] = y_pre[(size_t)base * 10 + i];
            for (int i = tid; i < rem * 5; i += TILE)
                s_true[i] = y_true[(size_t)base * 5 + i];
        }
        __syncthreads();

        if (tid < rem)
            acc += cell_loss(s_pre + tid * 10, s_true + tid * 5, base + tid);

        __syncthreads();   // before next tile overwrites smem
    }

    // ---- block reduction ----
    #pragma unroll
    for (int off = 16; off > 0; off >>= 1)
        acc += __shfl_down_sync(0xFFFFFFFFu, acc, off);

    __shared__ float warp_sums[TILE / 32];
    int lane = tid & 31;
    int wid = tid >> 5;
    if (lane == 0) warp_sums[wid] = acc;
    __syncthreads();

    if (wid == 0) {
        float v = (lane < TILE / 32) ? warp_sums[lane] : 0.0f;
        #pragma unroll
        for (int off = 4; off > 0; off >>= 1)
            v += __shfl_down_sync(0xFFFFFFFFu, v, off);
        if (lane == 0) g_partials[blockIdx.x] = v;
    }
}

__global__ void __launch_bounds__(256)
finalize_kernel(float* out, int n_partials, float inv_b) {
    int tid = threadIdx.x;
    double s = 0.0;
    for (int i = tid; i < n_partials; i += 256)
        s += (double)g_partials[i];

    #pragma unroll
    for (int off = 16; off > 0; off >>= 1)
        s += __shfl_down_sync(0xFFFFFFFFu, s, off);

    __shared__ double wsum[8];
    int lane = tid & 31;
    int wid = tid >> 5;
    if (lane == 0) wsum[wid] = s;
    __syncthreads();
    if (wid == 0) {
        double v = (lane < 8) ? wsum[lane] : 0.0;
        #pragma unroll
        for (int off = 4; off > 0; off >>= 1)
            v += __shfl_down_sync(0xFFFFFFFFu, v, off);
        if (lane == 0) out[0] = (float)(v * (double)inv_b);
    }
}

extern "C" void kernel_launch(void* const* d_in, const int* in_sizes, int n_in,
                              void* d_out, int out_size) {
    const float* y_pre = (const float*)d_in[0];
    const float* y_true = (const float*)d_in[1];
    float* out = (float*)d_out;

    int n_cells = in_sizes[1] / 5;               // B * 49
    int B = n_cells / CELLS_PER_IMG;
    int n_tiles = (n_cells + TILE - 1) / TILE;

    int grid = 148 * 8;                          // 8 blocks/SM, full occupancy
    if (grid > n_tiles) grid = n_tiles;
    if (grid > MAX_BLOCKS) grid = MAX_BLOCKS;

    yolo_loss_kernel<<<grid, TILE>>>(y_pre, y_true, n_cells, n_tiles);
    finalize_kernel<<<1, 256>>>(out, grid, 1.0f / (float)B);
}

// round 3
// speedup vs baseline: 1.1041x; 1.1041x over previous
#include <cuda_runtime.h>

#define GRID_NUM 7
#define CELLS_PER_IMG 49
#define IMG_SIZE 448.0f
#define GRID_SIZE 64.0f
#define LAMBDA_COORD 5.0f
#define LAMBDA_NOOBJ 0.1f
#define EPSF 1e-12f

#define NTHREADS 256
#define MAX_BLOCKS 2048

__device__ float g_partials[MAX_BLOCKS];
__device__ unsigned int g_ticket;   // zero-initialized in cubin; reset by last block

__device__ __forceinline__ float iou_f(float bx, float by, float bw, float bh,
                                       float tx, float ty, float tw, float th,
                                       float gi, float gj) {
    float cx_p = bx * GRID_SIZE + gj * GRID_SIZE;
    float cy_p = by * GRID_SIZE + gi * GRID_SIZE;
    float w_p = bw * IMG_SIZE;
    float h_p = bh * IMG_SIZE;
    float x0p = cx_p - w_p * 0.5f, x1p = cx_p + w_p * 0.5f;
    float y0p = cy_p - h_p * 0.5f, y1p = cy_p + h_p * 0.5f;
    float cx_t = tx * GRID_SIZE + gj * GRID_SIZE;
    float cy_t = ty * GRID_SIZE + gi * GRID_SIZE;
    float w_t = tw * IMG_SIZE;
    float h_t = th * IMG_SIZE;
    float x0t = cx_t - w_t * 0.5f, x1t = cx_t + w_t * 0.5f;
    float y0t = cy_t - h_t * 0.5f;
    float y1t = cy_t + w_t * 0.5f;   // TYPO kept from reference: uses w_t
    float ux0 = fmaxf(x0p, x0t);
    float ux1 = fminf(x1p, x1t);
    float uy0 = fmaxf(y0p, y0t);
    float uy1 = fminf(y1p, y1t);
    bool valid = (ux0 < ux1) && (uy0 < uy1);
    float area_u = (ux1 - ux0) * (uy1 - uy0);
    float area_p = (x1p - x0p) * (y1p - y0p);
    float area_t = (x1t - x0t) * (y1t - y0t);
    float res = area_u / (area_p + area_t - area_u + EPSF);
    return valid ? res : 0.0f;
}

__global__ void __launch_bounds__(NTHREADS)
yolo_loss_fused(const float* __restrict__ y_pre,
                const float* __restrict__ y_true,
                int n_cells, float inv_b, float* __restrict__ out) {
    int tid = threadIdx.x;
    int stride = gridDim.x * NTHREADS;
    float acc = 0.0f;

    for (int idx = blockIdx.x * NTHREADS + tid; idx < n_cells; idx += stride) {
        int g = idx % CELLS_PER_IMG;
        float gi = (float)(g / GRID_NUM);
        float gj = (float)(g % GRID_NUM);

        // y_pre cell: 10 floats, 40B stride -> 8B aligned -> float2 loads
        const float2* p = (const float2*)(y_pre + (size_t)idx * 10);
        float2 p01 = p[0];
        float2 p23 = p[1];
        float2 p45 = p[2];
        float2 p67 = p[3];
        float2 p89 = p[4];

        const float* t = y_true + (size_t)idx * 5;
        float t0 = t[0], t1 = t[1], t2 = t[2], t3 = t[3], t4 = t[4];

        float iou0 = iou_f(p01.x, p01.y, p23.x, p23.y, t0, t1, t2, t3, gi, gj);
        float iou1 = iou_f(p45.y, p67.x, p67.y, p89.x, t0, t1, t2, t3, gi, gj);

        bool obj = (t4 == 1.0f);
        bool c0 = iou0 > iou1;

        float local;
        if (obj) {
            float conf_pre = c0 ? p45.x : p89.y;
            float conf_true = c0 ? iou0 : iou1;
            float dc = conf_pre - conf_true;
            local = dc * dc;
            float xb = c0 ? p01.x : p45.y;
            float yb = c0 ? p01.y : p67.x;
            float dx = xb - t0;
            float dy = yb - t1;
            local += LAMBDA_COORD * (dx * dx + dy * dy);
            float wb = fmaxf(c0 ? p23.x : p67.y, EPSF);
            float hb = fmaxf(c0 ? p23.y : p89.x, EPSF);
            float wt = fmaxf(t2, EPSF);
            float ht = fmaxf(t3, EPSF);
            float dw = sqrtf(wb) - sqrtf(wt);
            float dh = sqrtf(hb) - sqrtf(ht);
            local += LAMBDA_COORD * (dw * dw + dh * dh);
        } else {
            local = LAMBDA_NOOBJ * (p45.x * p45.x + p89.y * p89.y);
        }
        acc += local;
    }

    // ---- block reduction (fp32) ----
    #pragma unroll
    for (int off = 16; off > 0; off >>= 1)
        acc += __shfl_down_sync(0xFFFFFFFFu, acc, off);

    __shared__ float warp_sums[NTHREADS / 32];
    __shared__ bool s_is_last;
    int lane = tid & 31;
    int wid = tid >> 5;
    if (lane == 0) warp_sums[wid] = acc;
    __syncthreads();

    if (tid == 0) {
        float v = 0.0f;
        #pragma unroll
        for (int i = 0; i < NTHREADS / 32; i++) v += warp_sums[i];
        g_partials[blockIdx.x] = v;
        __threadfence();
        unsigned int prev = atomicInc(&g_ticket, 0xFFFFFFFFu);
        s_is_last = (prev == gridDim.x - 1);
    }
    __syncthreads();

    // ---- last block reduces all partials in double and finalizes ----
    if (s_is_last) {
        int nb = gridDim.x;
        double s = 0.0;
        for (int i = tid; i < nb; i += NTHREADS)
            s += (double)g_partials[i];

        #pragma unroll
        for (int off = 16; off > 0; off >>= 1)
            s += __shfl_down_sync(0xFFFFFFFFu, s, off);

        __shared__ double wsum[NTHREADS / 32];
        if (lane == 0) wsum[wid] = s;
        __syncthreads();
        if (tid == 0) {
            double v = 0.0;
            #pragma unroll
            for (int i = 0; i < NTHREADS / 32; i++) v += wsum[i];
            out[0] = (float)(v * (double)inv_b);
            __threadfence();
            g_ticket = 0;   // reset for next graph replay (deterministic)
        }
    }
}

extern "C" void kernel_launch(void* const* d_in, const int* in_sizes, int n_in,
                              void* d_out, int out_size) {
    const float* y_pre = (const float*)d_in[0];
    const float* y_true = (const float*)d_in[1];
    float* out = (float*)d_out;

    int n_cells = in_sizes[1] / 5;               // B * 49
    int B = n_cells / CELLS_PER_IMG;

    int grid = 148 * 8;                          // 8 blocks/SM
    int max_useful = (n_cells + NTHREADS - 1) / NTHREADS;
    if (grid > max_useful) grid = max_useful;
    if (grid > MAX_BLOCKS) grid = MAX_BLOCKS;

    yolo_loss_fused<<<grid, NTHREADS>>>(y_pre, y_true, n_cells,
                                        1.0f / (float)B, out);
}